// round 4
// baseline (speedup 1.0000x reference)
#include <cuda_runtime.h>
#include <math.h>
#include <stdint.h>

// Problem constants
#define BB 32
#define NN 128
#define DD 512
#define KK 8
#define ROWS (BB * NN)                 // 4096
#define PLANE (KK * NN * NN)           // 131072 elems per batch in [B,K,N,N]
#define ALPHA_OFF ((size_t)BB * PLANE) // 4194304

// Scratch (static device allocations are allowed; cudaMalloc is not)
__device__ float g_fused[(size_t)ROWS * DD];          //  8.4 MB
__device__ float g_q[(size_t)KK * ROWS * DD];         // 67.1 MB
__device__ float g_k[(size_t)KK * ROWS * DD];         // 67.1 MB
__device__ float g_invq[KK * ROWS];
__device__ float g_invk[KK * ROWS];

// ---------------------------------------------------------------------------
// Kernel 1: fused = [desc | nv] @ fusion_w^T + fusion_b
//   C[r,d] = sum_e A[r,e] * fusion_w[d,e],  r<4096, d<512, e<1024
//   128x128 tile, 256 threads, 8x8 per thread, BK=8
// ---------------------------------------------------------------------------
__global__ __launch_bounds__(256) void fusion_gemm(
    const float* __restrict__ desc, const float* __restrict__ nv,
    const float* __restrict__ fw, const float* __restrict__ fb)
{
    __shared__ float As[8][128];
    __shared__ float Bs[8][128];

    const int tid = threadIdx.x;
    const int tx = tid & 15;
    const int ty = tid >> 4;
    const int bm = blockIdx.y * 128;   // row block
    const int bn = blockIdx.x * 128;   // out-dim block

    float acc[8][8];
#pragma unroll
    for (int i = 0; i < 8; i++)
#pragma unroll
        for (int j = 0; j < 8; j++) acc[i][j] = 0.0f;

    const int lr  = tid >> 1;          // 0..127
    const int le4 = (tid & 1) * 4;     // 0 or 4

    for (int k0 = 0; k0 < 2 * DD; k0 += 8) {
        // A tile: [128 rows x 8 e], store transposed As[e][row]
        int ge = k0 + le4;
        const float* asrc = (ge < DD)
            ? (desc + (size_t)(bm + lr) * DD + ge)
            : (nv   + (size_t)(bm + lr) * DD + (ge - DD));
        float4 av = *(const float4*)asrc;
        As[le4 + 0][lr] = av.x; As[le4 + 1][lr] = av.y;
        As[le4 + 2][lr] = av.z; As[le4 + 3][lr] = av.w;

        // B tile: Bt[e,d] = fw[d, e]; load per-d rows, store transposed Bs[e][d]
        float4 bv = *(const float4*)(fw + (size_t)(bn + lr) * (2 * DD) + k0 + le4);
        Bs[le4 + 0][lr] = bv.x; Bs[le4 + 1][lr] = bv.y;
        Bs[le4 + 2][lr] = bv.z; Bs[le4 + 3][lr] = bv.w;

        __syncthreads();
#pragma unroll
        for (int kk = 0; kk < 8; kk++) {
            float a[8], b[8];
            *(float4*)(a)     = *(const float4*)&As[kk][ty * 4];
            *(float4*)(a + 4) = *(const float4*)&As[kk][64 + ty * 4];
            *(float4*)(b)     = *(const float4*)&Bs[kk][tx * 4];
            *(float4*)(b + 4) = *(const float4*)&Bs[kk][64 + tx * 4];
#pragma unroll
            for (int i = 0; i < 8; i++)
#pragma unroll
                for (int j = 0; j < 8; j++) acc[i][j] += a[i] * b[j];
        }
        __syncthreads();
    }

    // Epilogue: add bias, store
#pragma unroll
    for (int ih = 0; ih < 2; ih++) {
#pragma unroll
        for (int ii = 0; ii < 4; ii++) {
            int r = bm + ih * 64 + ty * 4 + ii;
            int i = ih * 4 + ii;
#pragma unroll
            for (int jh = 0; jh < 2; jh++) {
                int c = bn + jh * 64 + tx * 4;
                float4 v;
                v.x = acc[i][jh * 4 + 0] + fb[c + 0];
                v.y = acc[i][jh * 4 + 1] + fb[c + 1];
                v.z = acc[i][jh * 4 + 2] + fb[c + 2];
                v.w = acc[i][jh * 4 + 3] + fb[c + 3];
                *(float4*)&g_fused[(size_t)r * DD + c] = v;
            }
        }
    }
}

// ---------------------------------------------------------------------------
// Kernel 2: q/k projections.  out[z][r,f] = sum_d g_fused[r,d] * W[z][d,f]
//   z in [0,16): z<8 -> W_q basis z -> g_q ; else W_k basis z-8 -> g_k
// ---------------------------------------------------------------------------
__global__ __launch_bounds__(256) void proj_gemm(
    const float* __restrict__ Wq, const float* __restrict__ Wk)
{
    __shared__ float As[8][128];
    __shared__ float Bs[8][128];

    const int tid = threadIdx.x;
    const int tx = tid & 15;
    const int ty = tid >> 4;
    const int bm = blockIdx.y * 128;   // row block (4096/128 = 32)
    const int bn = blockIdx.x * 128;   // f block   (512/128  = 4)
    const int z  = blockIdx.z;         // 0..15

    const float* W   = (z < KK) ? (Wq + (size_t)z * DD * DD)
                                : (Wk + (size_t)(z - KK) * DD * DD);
    float* out       = (z < KK) ? (g_q + (size_t)z * ROWS * DD)
                                : (g_k + (size_t)(z - KK) * ROWS * DD);

    float acc[8][8];
#pragma unroll
    for (int i = 0; i < 8; i++)
#pragma unroll
        for (int j = 0; j < 8; j++) acc[i][j] = 0.0f;

    const int lr  = tid >> 1;
    const int le4 = (tid & 1) * 4;
    const int bdd = tid >> 5;          // 0..7
    const int bf4 = (tid & 31) * 4;    // 0..124 step 4

    for (int k0 = 0; k0 < DD; k0 += 8) {
        // A tile transposed
        float4 av = *(const float4*)(g_fused + (size_t)(bm + lr) * DD + k0 + le4);
        As[le4 + 0][lr] = av.x; As[le4 + 1][lr] = av.y;
        As[le4 + 2][lr] = av.z; As[le4 + 3][lr] = av.w;

        // B tile: W[(k0+dd), f] contiguous in f
        float4 bv = *(const float4*)(W + (size_t)(k0 + bdd) * DD + bn + bf4);
        *(float4*)&Bs[bdd][bf4] = bv;

        __syncthreads();
#pragma unroll
        for (int kk = 0; kk < 8; kk++) {
            float a[8], b[8];
            *(float4*)(a)     = *(const float4*)&As[kk][ty * 4];
            *(float4*)(a + 4) = *(const float4*)&As[kk][64 + ty * 4];
            *(float4*)(b)     = *(const float4*)&Bs[kk][tx * 4];
            *(float4*)(b + 4) = *(const float4*)&Bs[kk][64 + tx * 4];
#pragma unroll
            for (int i = 0; i < 8; i++)
#pragma unroll
                for (int j = 0; j < 8; j++) acc[i][j] += a[i] * b[j];
        }
        __syncthreads();
    }

#pragma unroll
    for (int ih = 0; ih < 2; ih++) {
#pragma unroll
        for (int ii = 0; ii < 4; ii++) {
            int r = bm + ih * 64 + ty * 4 + ii;
            int i = ih * 4 + ii;
#pragma unroll
            for (int jh = 0; jh < 2; jh++) {
                int c = bn + jh * 64 + tx * 4;
                float4 v;
                v.x = acc[i][jh * 4 + 0];
                v.y = acc[i][jh * 4 + 1];
                v.z = acc[i][jh * 4 + 2];
                v.w = acc[i][jh * 4 + 3];
                *(float4*)&out[(size_t)r * DD + c] = v;
            }
        }
    }
}

// ---------------------------------------------------------------------------
// Kernel 3: per-row inverse L2 norms for g_q and g_k (one warp per row)
// ---------------------------------------------------------------------------
__global__ __launch_bounds__(256) void rownorm_kernel()
{
    const int gwarp = (blockIdx.x * blockDim.x + threadIdx.x) >> 5;
    const int lane = threadIdx.x & 31;
    if (gwarp >= 2 * KK * ROWS) return;

    const float* p;
    float* inv;
    int idx;
    if (gwarp < KK * ROWS) { p = g_q; inv = g_invq; idx = gwarp; }
    else                   { p = g_k; inv = g_invk; idx = gwarp - KK * ROWS; }

    const float4* row = (const float4*)(p + (size_t)idx * DD);
    float s = 0.0f;
#pragma unroll
    for (int j = 0; j < 4; j++) {
        float4 v = row[lane + 32 * j];
        s += v.x * v.x + v.y * v.y + v.z * v.z + v.w * v.w;
    }
#pragma unroll
    for (int m = 16; m; m >>= 1) s += __shfl_xor_sync(0xffffffffu, s, m);
    if (lane == 0) inv[idx] = 1.0f / fmaxf(sqrtf(s), 1e-12f);
}

// ---------------------------------------------------------------------------
// Kernel 4: logits = (qn . kn) * scale ; softmax over m ; write alpha.
//   One block per (basis kb, batch b): full 128x128x512 NT GEMM + reg softmax.
// ---------------------------------------------------------------------------
__global__ __launch_bounds__(256) void attn_softmax(float* __restrict__ out)
{
    __shared__ float As[8][128];
    __shared__ float Bs[8][128];

    const int kb = blockIdx.x;  // 0..7
    const int b  = blockIdx.y;  // 0..31
    const int tid = threadIdx.x;
    const int tx = tid & 15;
    const int ty = tid >> 4;

    const float* qp = g_q + ((size_t)kb * ROWS + (size_t)b * NN) * DD;
    const float* kp = g_k + ((size_t)kb * ROWS + (size_t)b * NN) * DD;

    float acc[8][8];
#pragma unroll
    for (int i = 0; i < 8; i++)
#pragma unroll
        for (int j = 0; j < 8; j++) acc[i][j] = 0.0f;

    const int lr  = tid >> 1;
    const int le4 = (tid & 1) * 4;

    for (int k0 = 0; k0 < DD; k0 += 8) {
        float4 av = *(const float4*)(qp + (size_t)lr * DD + k0 + le4);
        As[le4 + 0][lr] = av.x; As[le4 + 1][lr] = av.y;
        As[le4 + 2][lr] = av.z; As[le4 + 3][lr] = av.w;
        float4 bv = *(const float4*)(kp + (size_t)lr * DD + k0 + le4);
        Bs[le4 + 0][lr] = bv.x; Bs[le4 + 1][lr] = bv.y;
        Bs[le4 + 2][lr] = bv.z; Bs[le4 + 3][lr] = bv.w;

        __syncthreads();
#pragma unroll
        for (int kk = 0; kk < 8; kk++) {
            float a[8], bb[8];
            *(float4*)(a)      = *(const float4*)&As[kk][ty * 4];
            *(float4*)(a + 4)  = *(const float4*)&As[kk][64 + ty * 4];
            *(float4*)(bb)     = *(const float4*)&Bs[kk][tx * 4];
            *(float4*)(bb + 4) = *(const float4*)&Bs[kk][64 + tx * 4];
#pragma unroll
            for (int i = 0; i < 8; i++)
#pragma unroll
                for (int j = 0; j < 8; j++) acc[i][j] += a[i] * bb[j];
        }
        __syncthreads();
    }

    const float SCALE = 0.04419417382415922f;  // 1/sqrt(512)
    const int invbase = kb * ROWS + b * NN;

    float iq[8], ik[8];
#pragma unroll
    for (int ih = 0; ih < 2; ih++)
#pragma unroll
        for (int ii = 0; ii < 4; ii++)
            iq[ih * 4 + ii] = g_invq[invbase + ih * 64 + ty * 4 + ii];
#pragma unroll
    for (int jh = 0; jh < 2; jh++)
#pragma unroll
        for (int jj = 0; jj < 4; jj++)
            ik[jh * 4 + jj] = g_invk[invbase + jh * 64 + tx * 4 + jj];

#pragma unroll
    for (int i = 0; i < 8; i++) {
        float si = iq[i] * SCALE;
#pragma unroll
        for (int j = 0; j < 8; j++) acc[i][j] *= si * ik[j];
    }

    // Row softmax: the 16 threads sharing a row are consecutive lanes
    // within a 16-lane half-warp (same ty). xor-shfl over {8,4,2,1}.
#pragma unroll
    for (int i = 0; i < 8; i++) {
        float m = acc[i][0];
#pragma unroll
        for (int j = 1; j < 8; j++) m = fmaxf(m, acc[i][j]);
#pragma unroll
        for (int msk = 8; msk; msk >>= 1)
            m = fmaxf(m, __shfl_xor_sync(0xffffffffu, m, msk));

        float e[8];
        float sum = 0.0f;
#pragma unroll
        for (int j = 0; j < 8; j++) { e[j] = __expf(acc[i][j] - m); sum += e[j]; }
#pragma unroll
        for (int msk = 8; msk; msk >>= 1)
            sum += __shfl_xor_sync(0xffffffffu, sum, msk);
        float rinv = 1.0f / sum;

        int r = (i < 4) ? (ty * 4 + i) : (64 + ty * 4 + (i - 4));
        size_t rowoff = ALPHA_OFF + (((size_t)b * KK + kb) * NN + r) * NN;
        float4 v0 = { e[0] * rinv, e[1] * rinv, e[2] * rinv, e[3] * rinv };
        float4 v1 = { e[4] * rinv, e[5] * rinv, e[6] * rinv, e[7] * rinv };
        *(float4*)&out[rowoff + tx * 4]      = v0;
        *(float4*)&out[rowoff + 64 + tx * 4] = v1;
    }
}

// ---------------------------------------------------------------------------
// Kernel 5: bias_log = log(max(0.01 * mean_b(alpha), 1e-6)) broadcast over b.
// ---------------------------------------------------------------------------
__global__ __launch_bounds__(256) void bias_kernel(float* __restrict__ out)
{
    const int idx = blockIdx.x * blockDim.x + threadIdx.x;  // 0..131071 = (kb,n,m)
    if (idx >= PLANE) return;
    float s = 0.0f;
#pragma unroll 8
    for (int b = 0; b < BB; b++)
        s += out[ALPHA_OFF + (size_t)b * PLANE + idx];
    float bias = logf(fmaxf(s * (0.01f / 32.0f), 1e-6f));
#pragma unroll 8
    for (int b = 0; b < BB; b++)
        out[(size_t)b * PLANE + idx] = bias;
}

// ---------------------------------------------------------------------------
// Launch
// ---------------------------------------------------------------------------
extern "C" void kernel_launch(void* const* d_in, const int* in_sizes, int n_in,
                              void* d_out, int out_size)
{
    const float* desc = (const float*)d_in[0];   // [32,128,512]
    const float* nv   = (const float*)d_in[1];   // [32,128,512]
    const float* Wq   = (const float*)d_in[2];   // [8,512,512]
    const float* Wk   = (const float*)d_in[3];   // [8,512,512]
    const float* fw   = (const float*)d_in[4];   // [512,1024]
    const float* fb   = (const float*)d_in[5];   // [512]
    float* out = (float*)d_out;                  // [bias_log | alpha], 2*B*K*N*N

    // 1. fusion MLP
    fusion_gemm<<<dim3(4, 32), 256>>>(desc, nv, fw, fb);

    // 2. q/k projections (16 batched GEMMs)
    proj_gemm<<<dim3(4, 32, 16), 256>>>(Wq, Wk);

    // 3. inverse row norms (2 * 8 * 4096 rows, 1 warp each)
    rownorm_kernel<<<(2 * KK * ROWS * 32) / 256, 256>>>();

    // 4. logits + softmax -> alpha
    attn_softmax<<<dim3(KK, BB), 256>>>(out);

    // 5. EMA mean + log -> bias_log (broadcast)
    bias_kernel<<<PLANE / 256, 256>>>(out);
}

// round 6
// speedup vs baseline: 4.5956x; 4.5956x over previous
#include <cuda_runtime.h>
#include <cuda_bf16.h>
#include <math.h>
#include <stdint.h>

// ---------------------------------------------------------------------------
// Problem constants
// ---------------------------------------------------------------------------
#define BB 32
#define NN 128
#define DD 512
#define KK 8
#define ROWS (BB * NN)                  // 4096
#define PLANE (KK * NN * NN)            // 131072
#define ALPHA_OFF ((size_t)BB * PLANE)  // 4194304

// Smem tile geometry: 128 rows x 32 k (bf16), rows padded to 80 bytes
// (64B data + 16B pad) -> conflict-free ldmatrix. One stage = A + B = 20480B.
#define ROWB 80
#define TILE_BYTES (128 * ROWB)          // 10240
#define STAGE_BYTES (2 * TILE_BYTES)     // 20480

// ---------------------------------------------------------------------------
// Scratch (static device globals; no cudaMalloc)
// ---------------------------------------------------------------------------
__device__ __nv_bfloat16 g_A0[(size_t)ROWS * 1024];     // concat(desc,nv) bf16
__device__ __nv_bfloat16 g_fwb[(size_t)DD * 1024];      // fusion_w bf16 [d][e]
__device__ __nv_bfloat16 g_Wt[(size_t)16 * DD * DD];    // W^T bf16 [z][f][d]
__device__ __nv_bfloat16 g_fusedb[(size_t)ROWS * DD];   // fused bf16
__device__ __nv_bfloat16 g_qk[(size_t)16 * ROWS * DD];  // q (z<8) then k
__device__ float g_inv[2 * KK * ROWS];                  // inv L2 norms, q then k

// ---------------------------------------------------------------------------
// PTX helpers (plain sm_100-safe: HMMA / ldmatrix / cp.async only)
// ---------------------------------------------------------------------------
__device__ __forceinline__ uint32_t smem_u32(const void* p) {
    uint32_t a;
    asm("{ .reg .u64 t; cvta.to.shared.u64 t, %1; cvt.u32.u64 %0, t; }"
        : "=r"(a) : "l"(p));
    return a;
}

__device__ __forceinline__ void cp16(uint32_t dst, const void* src) {
    asm volatile("cp.async.cg.shared.global [%0], [%1], 16;"
                 :: "r"(dst), "l"(src));
}
#define CP_COMMIT() asm volatile("cp.async.commit_group;" ::: "memory")
#define CP_WAIT1()  asm volatile("cp.async.wait_group 1;" ::: "memory")
#define CP_WAIT0()  asm volatile("cp.async.wait_group 0;" ::: "memory")

__device__ __forceinline__ void ldsm4(uint32_t* r, uint32_t addr) {
    asm volatile("ldmatrix.sync.aligned.m8n8.x4.shared.b16 {%0,%1,%2,%3}, [%4];"
                 : "=r"(r[0]), "=r"(r[1]), "=r"(r[2]), "=r"(r[3]) : "r"(addr));
}

__device__ __forceinline__ void mma_bf16(float* d, const uint32_t* a,
                                         uint32_t b0, uint32_t b1) {
    asm volatile(
        "mma.sync.aligned.m16n8k16.row.col.f32.bf16.bf16.f32 "
        "{%0,%1,%2,%3}, {%4,%5,%6,%7}, {%8,%9}, {%0,%1,%2,%3};"
        : "+f"(d[0]), "+f"(d[1]), "+f"(d[2]), "+f"(d[3])
        : "r"(a[0]), "r"(a[1]), "r"(a[2]), "r"(a[3]), "r"(b0), "r"(b1));
}

// Load one 128x32 A tile + 128x32 B tile into a smem stage (256 threads).
__device__ __forceinline__ void load_tile(uint32_t sdst,
                                          const __nv_bfloat16* gA, int ldA,
                                          const __nv_bfloat16* gB, int ldB,
                                          int tid) {
#pragma unroll
    for (int h = 0; h < 2; h++) {
        int c = tid + h * 256;          // 0..511
        int row = c >> 2, q = c & 3;    // 4 x 16B chunks per 64B row
        cp16(sdst + row * ROWB + q * 16, gA + (size_t)row * ldA + q * 8);
        cp16(sdst + TILE_BYTES + row * ROWB + q * 16,
             gB + (size_t)row * ldB + q * 8);
    }
}

// ---------------------------------------------------------------------------
// Prep kernels
// ---------------------------------------------------------------------------
__global__ __launch_bounds__(256) void convert_inputs(
    const float* __restrict__ desc, const float* __restrict__ nv,
    const float* __restrict__ fw) {
    size_t base = ((size_t)blockIdx.x * blockDim.x + threadIdx.x) * 8;
    if (base >= (size_t)(ROWS + DD) * 1024) return;
    int r = (int)(base >> 10);
    int c = (int)(base & 1023);
    const float* src;
    __nv_bfloat16* dst;
    if (r < ROWS) {
        src = (c < DD) ? (desc + (size_t)r * DD + c)
                       : (nv + (size_t)r * DD + (c - DD));
        dst = g_A0 + ((size_t)r << 10) + c;
    } else {
        src = fw + (size_t)(r - ROWS) * 1024 + c;
        dst = g_fwb + (size_t)(r - ROWS) * 1024 + c;
    }
    float4 v0 = *(const float4*)src;
    float4 v1 = *(const float4*)(src + 4);
    uint32_t pk[4];
    __nv_bfloat162 h;
    h = __float22bfloat162_rn(make_float2(v0.x, v0.y)); pk[0] = *(uint32_t*)&h;
    h = __float22bfloat162_rn(make_float2(v0.z, v0.w)); pk[1] = *(uint32_t*)&h;
    h = __float22bfloat162_rn(make_float2(v1.x, v1.y)); pk[2] = *(uint32_t*)&h;
    h = __float22bfloat162_rn(make_float2(v1.z, v1.w)); pk[3] = *(uint32_t*)&h;
    *(uint4*)dst = *(uint4*)pk;
}

// Wt[z][f][d] = W[z][d][f] as bf16 (B operand must be K(=d)-contiguous).
__global__ __launch_bounds__(256) void transpose_w(
    const float* __restrict__ Wq, const float* __restrict__ Wk) {
    __shared__ float t[32][33];
    int z = blockIdx.z;
    const float* W = (z < KK) ? (Wq + (size_t)z * DD * DD)
                              : (Wk + (size_t)(z - KK) * DD * DD);
    __nv_bfloat16* o = g_Wt + (size_t)z * DD * DD;
    int d0 = blockIdx.x * 32, f0 = blockIdx.y * 32;
    int tx = threadIdx.x, ty = threadIdx.y;
#pragma unroll
    for (int j = 0; j < 32; j += 8)
        t[ty + j][tx] = W[(size_t)(d0 + ty + j) * DD + f0 + tx];
    __syncthreads();
#pragma unroll
    for (int j = 0; j < 32; j += 8)
        o[(size_t)(f0 + ty + j) * DD + d0 + tx] = __float2bfloat16(t[tx][ty + j]);
}

// Per-row inverse L2 norms over bf16 q/k rows (1 warp / row).
__global__ __launch_bounds__(256) void rownorm_kernel() {
    int gw = (int)((blockIdx.x * blockDim.x + threadIdx.x) >> 5);
    int lane = threadIdx.x & 31;
    if (gw >= 16 * ROWS) return;
    const uint4* row = (const uint4*)(g_qk + (size_t)gw * DD);
    float s = 0.f;
#pragma unroll
    for (int j = 0; j < 2; j++) {
        uint4 v = row[lane + 32 * j];
        uint32_t w[4] = {v.x, v.y, v.z, v.w};
#pragma unroll
        for (int q = 0; q < 4; q++) {
            float2 f = __bfloat1622float2(*(__nv_bfloat162*)&w[q]);
            s += f.x * f.x + f.y * f.y;
        }
    }
#pragma unroll
    for (int m = 16; m; m >>= 1) s += __shfl_xor_sync(0xffffffffu, s, m);
    if (lane == 0) g_inv[gw] = 1.0f / fmaxf(sqrtf(s), 1e-12f);
}

// ---------------------------------------------------------------------------
// 128x128 HMMA GEMM, 4x2 warp grid (warp tile 32x64), bf16 epilogue.
// ---------------------------------------------------------------------------
__device__ __forceinline__ void gemm_4x2_body(
    char* smem, const __nv_bfloat16* gA, int ldA,
    const __nv_bfloat16* gB, int ldB, int KT, float acc[2][8][4]) {
    const uint32_t sb = smem_u32(smem);
    const int tid = threadIdx.x, lane = tid & 31, wid = tid >> 5;
    const int wm = wid >> 1, wn = wid & 1;

    load_tile(sb, gA, ldA, gB, ldB, tid);
    CP_COMMIT();
    if (KT > 1) {
        load_tile(sb + STAGE_BYTES, gA + 32, ldA, gB + 32, ldB, tid);
        CP_COMMIT();
    }

#pragma unroll 1
    for (int kt = 0; kt < KT; kt++) {
        if (kt + 1 < KT) CP_WAIT1(); else CP_WAIT0();
        __syncthreads();
        const uint32_t sA = sb + (kt & 1) * STAGE_BYTES;
        const uint32_t sB = sA + TILE_BYTES;
#pragma unroll
        for (int ks = 0; ks < 2; ks++) {
            const int ko = ks * 32 + (lane >> 4) * 16;
            uint32_t a[2][4], bf[4][4];
#pragma unroll
            for (int i = 0; i < 2; i++)
                ldsm4(a[i], sA + (wm * 32 + i * 16 + (lane & 15)) * ROWB + ko);
#pragma unroll
            for (int j = 0; j < 4; j++)
                ldsm4(bf[j], sB + (wn * 64 + j * 16 + (lane & 15)) * ROWB + ko);
#pragma unroll
            for (int i = 0; i < 2; i++)
#pragma unroll
                for (int j = 0; j < 4; j++) {
                    mma_bf16(acc[i][2 * j],     a[i], bf[j][0], bf[j][2]);
                    mma_bf16(acc[i][2 * j + 1], a[i], bf[j][1], bf[j][3]);
                }
        }
        __syncthreads();
        if (kt + 2 < KT) {
            load_tile(sb + (kt & 1) * STAGE_BYTES,
                      gA + (kt + 2) * 32, ldA, gB + (kt + 2) * 32, ldB, tid);
            CP_COMMIT();
        }
    }
}

// Store 128x128 fp32 accum tile as bf16 (optional bias indexed by local col).
__device__ __forceinline__ void epilogue_bf16(
    float acc[2][8][4], __nv_bfloat16* outp, int ld, const float* bias) {
    const int lane = threadIdx.x & 31, wid = threadIdx.x >> 5;
    const int wm = wid >> 1, wn = wid & 1;
    const int qr = lane >> 2, qc = (lane & 3) * 2;
#pragma unroll
    for (int i = 0; i < 2; i++) {
        const int r0 = wm * 32 + i * 16 + qr;
#pragma unroll
        for (int n8 = 0; n8 < 8; n8++) {
            const int col = wn * 64 + n8 * 8 + qc;
            float b0 = 0.f, b1 = 0.f;
            if (bias) { b0 = __ldg(bias + col); b1 = __ldg(bias + col + 1); }
            __nv_bfloat162 h0 = __float22bfloat162_rn(
                make_float2(acc[i][n8][0] + b0, acc[i][n8][1] + b1));
            __nv_bfloat162 h1 = __float22bfloat162_rn(
                make_float2(acc[i][n8][2] + b0, acc[i][n8][3] + b1));
            *(uint32_t*)(outp + (size_t)r0 * ld + col) = *(uint32_t*)&h0;
            *(uint32_t*)(outp + (size_t)(r0 + 8) * ld + col) = *(uint32_t*)&h1;
        }
    }
}

__global__ __launch_bounds__(256, 2) void fusion_mma_kernel(
    const float* __restrict__ fb) {
    __shared__ char smem[2 * STAGE_BYTES];
    const int bn = blockIdx.x * 128, bm = blockIdx.y * 128;
    float acc[2][8][4];
#pragma unroll
    for (int i = 0; i < 2; i++)
#pragma unroll
        for (int j = 0; j < 8; j++)
#pragma unroll
            for (int e = 0; e < 4; e++) acc[i][j][e] = 0.f;
    gemm_4x2_body(smem, g_A0 + (size_t)bm * 1024, 1024,
                  g_fwb + (size_t)bn * 1024, 1024, 32, acc);
    epilogue_bf16(acc, g_fusedb + (size_t)bm * DD + bn, DD, fb + bn);
}

__global__ __launch_bounds__(256, 2) void proj_mma_kernel() {
    __shared__ char smem[2 * STAGE_BYTES];
    const int bn = blockIdx.x * 128, bm = blockIdx.y * 128, z = blockIdx.z;
    float acc[2][8][4];
#pragma unroll
    for (int i = 0; i < 2; i++)
#pragma unroll
        for (int j = 0; j < 8; j++)
#pragma unroll
            for (int e = 0; e < 4; e++) acc[i][j][e] = 0.f;
    gemm_4x2_body(smem, g_fusedb + (size_t)bm * DD, DD,
                  g_Wt + (size_t)z * DD * DD + (size_t)bn * DD, DD, 16, acc);
    epilogue_bf16(acc, g_qk + (size_t)z * ROWS * DD + (size_t)bm * DD + bn,
                  DD, nullptr);
}

// ---------------------------------------------------------------------------
// Attention: 128x128x512 HMMA + fused scaling/softmax. 8x1 warp grid so each
// output row's 128 values live in one warp quad (shfl-only reductions).
// ---------------------------------------------------------------------------
__global__ __launch_bounds__(256, 1) void attn_mma_kernel(float* __restrict__ out) {
    __shared__ char smem[2 * STAGE_BYTES];
    __shared__ float sq[128], sk[128];
    const int kb = blockIdx.x, b = blockIdx.y;
    const int tid = threadIdx.x, lane = tid & 31, wid = tid >> 5;

    const __nv_bfloat16* qp = g_qk + ((size_t)kb * ROWS + (size_t)b * NN) * DD;
    const __nv_bfloat16* kp = g_qk + ((size_t)(KK + kb) * ROWS + (size_t)b * NN) * DD;

    const int base = kb * ROWS + b * NN;
    const float SCALE = 0.04419417382415922f;  // 1/sqrt(512)
    if (tid < 128) {
        sq[tid] = g_inv[base + tid] * SCALE;
        sk[tid] = g_inv[KK * ROWS + base + tid];
    }

    const uint32_t sb = smem_u32(smem);
    load_tile(sb, qp, DD, kp, DD, tid);
    CP_COMMIT();
    load_tile(sb + STAGE_BYTES, qp + 32, DD, kp + 32, DD, tid);
    CP_COMMIT();

    float acc[16][4];
#pragma unroll
    for (int j = 0; j < 16; j++)
#pragma unroll
        for (int e = 0; e < 4; e++) acc[j][e] = 0.f;

#pragma unroll 1
    for (int kt = 0; kt < 16; kt++) {
        if (kt + 1 < 16) CP_WAIT1(); else CP_WAIT0();
        __syncthreads();
        const uint32_t sA = sb + (kt & 1) * STAGE_BYTES;
        const uint32_t sB = sA + TILE_BYTES;
#pragma unroll
        for (int ks = 0; ks < 2; ks++) {
            const int ko = ks * 32 + (lane >> 4) * 16;
            uint32_t a[4], bf[8][4];
            ldsm4(a, sA + (wid * 16 + (lane & 15)) * ROWB + ko);
#pragma unroll
            for (int j = 0; j < 8; j++)
                ldsm4(bf[j], sB + (j * 16 + (lane & 15)) * ROWB + ko);
#pragma unroll
            for (int j = 0; j < 8; j++) {
                mma_bf16(acc[2 * j],     a, bf[j][0], bf[j][2]);
                mma_bf16(acc[2 * j + 1], a, bf[j][1], bf[j][3]);
            }
        }
        __syncthreads();
        if (kt + 2 < 16) {
            load_tile(sb + (kt & 1) * STAGE_BYTES,
                      qp + (kt + 2) * 32, DD, kp + (kt + 2) * 32, DD, tid);
            CP_COMMIT();
        }
    }

    // Scale by norms; softmax. Thread owns rows r0, r0+8; cols n8*8+qc(+1).
    const int qr = lane >> 2, qc = (lane & 3) * 2;
    const int r0 = wid * 16 + qr, r1 = r0 + 8;
    const float si0 = sq[r0], si1 = sq[r1];

    float m0 = -1e30f, m1 = -1e30f;
#pragma unroll
    for (int n8 = 0; n8 < 16; n8++) {
        const int col = n8 * 8 + qc;
        const float k0 = sk[col], k1 = sk[col + 1];
        acc[n8][0] *= si0 * k0; acc[n8][1] *= si0 * k1;
        acc[n8][2] *= si1 * k0; acc[n8][3] *= si1 * k1;
        m0 = fmaxf(m0, fmaxf(acc[n8][0], acc[n8][1]));
        m1 = fmaxf(m1, fmaxf(acc[n8][2], acc[n8][3]));
    }
#pragma unroll
    for (int msk = 1; msk <= 2; msk <<= 1) {
        m0 = fmaxf(m0, __shfl_xor_sync(0xffffffffu, m0, msk));
        m1 = fmaxf(m1, __shfl_xor_sync(0xffffffffu, m1, msk));
    }
    float s0 = 0.f, s1 = 0.f;
#pragma unroll
    for (int n8 = 0; n8 < 16; n8++) {
        acc[n8][0] = __expf(acc[n8][0] - m0); s0 += acc[n8][0];
        acc[n8][1] = __expf(acc[n8][1] - m0); s0 += acc[n8][1];
        acc[n8][2] = __expf(acc[n8][2] - m1); s1 += acc[n8][2];
        acc[n8][3] = __expf(acc[n8][3] - m1); s1 += acc[n8][3];
    }
#pragma unroll
    for (int msk = 1; msk <= 2; msk <<= 1) {
        s0 += __shfl_xor_sync(0xffffffffu, s0, msk);
        s1 += __shfl_xor_sync(0xffffffffu, s1, msk);
    }
    const float i0 = 1.0f / s0, i1 = 1.0f / s1;

    float* o0 = out + ALPHA_OFF + (((size_t)b * KK + kb) * NN + r0) * NN;
    float* o1 = out + ALPHA_OFF + (((size_t)b * KK + kb) * NN + r1) * NN;
#pragma unroll
    for (int n8 = 0; n8 < 16; n8++) {
        const int col = n8 * 8 + qc;
        float2 v0 = {acc[n8][0] * i0, acc[n8][1] * i0};
        float2 v1 = {acc[n8][2] * i1, acc[n8][3] * i1};
        *(float2*)(o0 + col) = v0;
        *(float2*)(o1 + col) = v1;
    }
}

// ---------------------------------------------------------------------------
// bias_log = log(max(0.01 * mean_b(alpha), 1e-6)) broadcast over b.
// ---------------------------------------------------------------------------
__global__ __launch_bounds__(256) void bias_kernel(float* __restrict__ out) {
    const int idx = blockIdx.x * blockDim.x + threadIdx.x;
    if (idx >= PLANE) return;
    float s = 0.0f;
#pragma unroll 8
    for (int b = 0; b < BB; b++)
        s += out[ALPHA_OFF + (size_t)b * PLANE + idx];
    float bias = logf(fmaxf(s * (0.01f / 32.0f), 1e-6f));
#pragma unroll 8
    for (int b = 0; b < BB; b++)
        out[(size_t)b * PLANE + idx] = bias;
}

// ---------------------------------------------------------------------------
// Launch
// ---------------------------------------------------------------------------
extern "C" void kernel_launch(void* const* d_in, const int* in_sizes, int n_in,
                              void* d_out, int out_size) {
    const float* desc = (const float*)d_in[0];   // [32,128,512]
    const float* nv   = (const float*)d_in[1];   // [32,128,512]
    const float* Wq   = (const float*)d_in[2];   // [8,512,512]
    const float* Wk   = (const float*)d_in[3];   // [8,512,512]
    const float* fw   = (const float*)d_in[4];   // [512,1024]
    const float* fb   = (const float*)d_in[5];   // [512]
    float* out = (float*)d_out;                  // [bias_log | alpha]

    // bf16 conversions: concat(desc,nv) + fusion_w, and W^T
    convert_inputs<<<2304, 256>>>(desc, nv, fw);
    transpose_w<<<dim3(16, 16, 16), dim3(32, 8)>>>(Wq, Wk);

    // fusion = [desc|nv] @ fw^T + fb  (HMMA, K=1024)
    fusion_mma_kernel<<<dim3(4, 32), 256>>>(fb);

    // q/k projections: 16 batched 4096x512x512 GEMMs (HMMA)
    proj_mma_kernel<<<dim3(4, 32, 16), 256>>>();

    // inverse row norms of bf16 q/k
    rownorm_kernel<<<8192, 256>>>();

    // logits + softmax -> alpha (HMMA + fused epilogue)
    attn_mma_kernel<<<dim3(8, 32), 256>>>(out);

    // EMA mean + log -> bias_log broadcast
    bias_kernel<<<PLANE / 256, 256>>>(out);
}

// round 7
// speedup vs baseline: 5.1468x; 1.1199x over previous
#include <cuda_runtime.h>
#include <cuda_bf16.h>
#include <math.h>
#include <stdint.h>

// ---------------------------------------------------------------------------
// Problem constants
// ---------------------------------------------------------------------------
#define BB 32
#define NN 128
#define DD 512
#define KK 8
#define ROWS (BB * NN)                  // 4096
#define PLANE (KK * NN * NN)            // 131072
#define ALPHA_OFF ((size_t)BB * PLANE)  // 4194304

// Smem tile geometry: 128 rows x 64 k (bf16), rows padded to 144 bytes
// (128B data + 16B pad) -> conflict-free ldmatrix (row starts at word-banks
// 0,4,8,...,28 within each 8-address phase). One stage = A + B = 36864B.
#define ROWB 144
#define TILE_BYTES (128 * ROWB)          // 18432
#define STAGE_BYTES (2 * TILE_BYTES)     // 36864
#define SMEM_BYTES (2 * STAGE_BYTES)     // 73728 (2 stages)

// ---------------------------------------------------------------------------
// Scratch (static device globals; no cudaMalloc)
// ---------------------------------------------------------------------------
__device__ __nv_bfloat16 g_A0[(size_t)ROWS * 1024];     // concat(desc,nv) bf16
__device__ __nv_bfloat16 g_fwb[(size_t)DD * 1024];      // fusion_w bf16 [d][e]
__device__ __nv_bfloat16 g_Wt[(size_t)16 * DD * DD];    // W^T bf16 [z][f][d]
__device__ __nv_bfloat16 g_fusedb[(size_t)ROWS * DD];   // fused bf16
__device__ __nv_bfloat16 g_qk[(size_t)16 * ROWS * DD];  // q (z<8) then k
__device__ float g_inv[2 * KK * ROWS];                  // inv L2 norms, q then k

// ---------------------------------------------------------------------------
// PTX helpers (plain sm_100-safe: HMMA / ldmatrix / cp.async only)
// ---------------------------------------------------------------------------
__device__ __forceinline__ uint32_t smem_u32(const void* p) {
    uint32_t a;
    asm("{ .reg .u64 t; cvta.to.shared.u64 t, %1; cvt.u32.u64 %0, t; }"
        : "=r"(a) : "l"(p));
    return a;
}

__device__ __forceinline__ void cp16(uint32_t dst, const void* src) {
    asm volatile("cp.async.cg.shared.global [%0], [%1], 16;"
                 :: "r"(dst), "l"(src));
}
#define CP_COMMIT() asm volatile("cp.async.commit_group;" ::: "memory")
#define CP_WAIT1()  asm volatile("cp.async.wait_group 1;" ::: "memory")
#define CP_WAIT0()  asm volatile("cp.async.wait_group 0;" ::: "memory")

__device__ __forceinline__ void ldsm4(uint32_t* r, uint32_t addr) {
    asm volatile("ldmatrix.sync.aligned.m8n8.x4.shared.b16 {%0,%1,%2,%3}, [%4];"
                 : "=r"(r[0]), "=r"(r[1]), "=r"(r[2]), "=r"(r[3]) : "r"(addr));
}

__device__ __forceinline__ void mma_bf16(float* d, const uint32_t* a,
                                         uint32_t b0, uint32_t b1) {
    asm volatile(
        "mma.sync.aligned.m16n8k16.row.col.f32.bf16.bf16.f32 "
        "{%0,%1,%2,%3}, {%4,%5,%6,%7}, {%8,%9}, {%0,%1,%2,%3};"
        : "+f"(d[0]), "+f"(d[1]), "+f"(d[2]), "+f"(d[3])
        : "r"(a[0]), "r"(a[1]), "r"(a[2]), "r"(a[3]), "r"(b0), "r"(b1));
}

// Load one 128x64 A tile + 128x64 B tile into a smem stage (256 threads).
__device__ __forceinline__ void load_tile(uint32_t sdst,
                                          const __nv_bfloat16* gA, int ldA,
                                          const __nv_bfloat16* gB, int ldB,
                                          int tid) {
#pragma unroll
    for (int h = 0; h < 4; h++) {
        int c = tid + h * 256;          // 0..1023
        int row = c >> 3, q = c & 7;    // 8 x 16B chunks per 128B row
        cp16(sdst + row * ROWB + q * 16, gA + (size_t)row * ldA + q * 8);
        cp16(sdst + TILE_BYTES + row * ROWB + q * 16,
             gB + (size_t)row * ldB + q * 8);
    }
}

// ---------------------------------------------------------------------------
// Prep kernels
// ---------------------------------------------------------------------------
__global__ __launch_bounds__(256) void convert_inputs(
    const float* __restrict__ desc, const float* __restrict__ nv,
    const float* __restrict__ fw) {
    size_t base = ((size_t)blockIdx.x * blockDim.x + threadIdx.x) * 8;
    if (base >= (size_t)(ROWS + DD) * 1024) return;
    int r = (int)(base >> 10);
    int c = (int)(base & 1023);
    const float* src;
    __nv_bfloat16* dst;
    if (r < ROWS) {
        src = (c < DD) ? (desc + (size_t)r * DD + c)
                       : (nv + (size_t)r * DD + (c - DD));
        dst = g_A0 + ((size_t)r << 10) + c;
    } else {
        src = fw + (size_t)(r - ROWS) * 1024 + c;
        dst = g_fwb + (size_t)(r - ROWS) * 1024 + c;
    }
    float4 v0 = *(const float4*)src;
    float4 v1 = *(const float4*)(src + 4);
    uint32_t pk[4];
    __nv_bfloat162 h;
    h = __float22bfloat162_rn(make_float2(v0.x, v0.y)); pk[0] = *(uint32_t*)&h;
    h = __float22bfloat162_rn(make_float2(v0.z, v0.w)); pk[1] = *(uint32_t*)&h;
    h = __float22bfloat162_rn(make_float2(v1.x, v1.y)); pk[2] = *(uint32_t*)&h;
    h = __float22bfloat162_rn(make_float2(v1.z, v1.w)); pk[3] = *(uint32_t*)&h;
    *(uint4*)dst = *(uint4*)pk;
}

// Wt[z][f][d] = W[z][d][f] as bf16 (B operand must be K(=d)-contiguous).
__global__ __launch_bounds__(256) void transpose_w(
    const float* __restrict__ Wq, const float* __restrict__ Wk) {
    __shared__ float t[32][33];
    int z = blockIdx.z;
    const float* W = (z < KK) ? (Wq + (size_t)z * DD * DD)
                              : (Wk + (size_t)(z - KK) * DD * DD);
    __nv_bfloat16* o = g_Wt + (size_t)z * DD * DD;
    int d0 = blockIdx.x * 32, f0 = blockIdx.y * 32;
    int tx = threadIdx.x, ty = threadIdx.y;
#pragma unroll
    for (int j = 0; j < 32; j += 8)
        t[ty + j][tx] = W[(size_t)(d0 + ty + j) * DD + f0 + tx];
    __syncthreads();
#pragma unroll
    for (int j = 0; j < 32; j += 8)
        o[(size_t)(f0 + ty + j) * DD + d0 + tx] = __float2bfloat16(t[tx][ty + j]);
}

// Per-row inverse L2 norms over bf16 q/k rows (1 warp / row).
__global__ __launch_bounds__(256) void rownorm_kernel() {
    int gw = (int)((blockIdx.x * blockDim.x + threadIdx.x) >> 5);
    int lane = threadIdx.x & 31;
    if (gw >= 16 * ROWS) return;
    const uint4* row = (const uint4*)(g_qk + (size_t)gw * DD);
    float s = 0.f;
#pragma unroll
    for (int j = 0; j < 2; j++) {
        uint4 v = row[lane + 32 * j];
        uint32_t w[4] = {v.x, v.y, v.z, v.w};
#pragma unroll
        for (int q = 0; q < 4; q++) {
            float2 f = __bfloat1622float2(*(__nv_bfloat162*)&w[q]);
            s += f.x * f.x + f.y * f.y;
        }
    }
#pragma unroll
    for (int m = 16; m; m >>= 1) s += __shfl_xor_sync(0xffffffffu, s, m);
    if (lane == 0) g_inv[gw] = 1.0f / fmaxf(sqrtf(s), 1e-12f);
}

// ---------------------------------------------------------------------------
// 128x128 HMMA GEMM, 4x2 warp grid (warp tile 32x64), K-chunks of 64,
// 2-stage cp.async pipeline.
// ---------------------------------------------------------------------------
__device__ __forceinline__ void gemm_4x2_body(
    char* smem, const __nv_bfloat16* gA, int ldA,
    const __nv_bfloat16* gB, int ldB, int KT, float acc[2][8][4]) {
    const uint32_t sb = smem_u32(smem);
    const int tid = threadIdx.x, lane = tid & 31, wid = tid >> 5;
    const int wm = wid >> 1, wn = wid & 1;

    load_tile(sb, gA, ldA, gB, ldB, tid);
    CP_COMMIT();
    if (KT > 1) {
        load_tile(sb + STAGE_BYTES, gA + 64, ldA, gB + 64, ldB, tid);
        CP_COMMIT();
    }

#pragma unroll 1
    for (int kt = 0; kt < KT; kt++) {
        if (kt + 1 < KT) CP_WAIT1(); else CP_WAIT0();
        __syncthreads();
        const uint32_t sA = sb + (kt & 1) * STAGE_BYTES;
        const uint32_t sB = sA + TILE_BYTES;
#pragma unroll
        for (int ks = 0; ks < 4; ks++) {
            const int ko = ks * 32 + (lane >> 4) * 16;
            uint32_t a[2][4], bf[4][4];
#pragma unroll
            for (int i = 0; i < 2; i++)
                ldsm4(a[i], sA + (wm * 32 + i * 16 + (lane & 15)) * ROWB + ko);
#pragma unroll
            for (int j = 0; j < 4; j++)
                ldsm4(bf[j], sB + (wn * 64 + j * 16 + (lane & 15)) * ROWB + ko);
#pragma unroll
            for (int i = 0; i < 2; i++)
#pragma unroll
                for (int j = 0; j < 4; j++) {
                    mma_bf16(acc[i][2 * j],     a[i], bf[j][0], bf[j][2]);
                    mma_bf16(acc[i][2 * j + 1], a[i], bf[j][1], bf[j][3]);
                }
        }
        __syncthreads();
        if (kt + 2 < KT) {
            load_tile(sb + (kt & 1) * STAGE_BYTES,
                      gA + (kt + 2) * 64, ldA, gB + (kt + 2) * 64, ldB, tid);
            CP_COMMIT();
        }
    }
}

// Store 128x128 fp32 accum tile as bf16 (optional bias indexed by local col).
__device__ __forceinline__ void epilogue_bf16(
    float acc[2][8][4], __nv_bfloat16* outp, int ld, const float* bias) {
    const int lane = threadIdx.x & 31, wid = threadIdx.x >> 5;
    const int wm = wid >> 1, wn = wid & 1;
    const int qr = lane >> 2, qc = (lane & 3) * 2;
#pragma unroll
    for (int i = 0; i < 2; i++) {
        const int r0 = wm * 32 + i * 16 + qr;
#pragma unroll
        for (int n8 = 0; n8 < 8; n8++) {
            const int col = wn * 64 + n8 * 8 + qc;
            float b0 = 0.f, b1 = 0.f;
            if (bias) { b0 = __ldg(bias + col); b1 = __ldg(bias + col + 1); }
            __nv_bfloat162 h0 = __float22bfloat162_rn(
                make_float2(acc[i][n8][0] + b0, acc[i][n8][1] + b1));
            __nv_bfloat162 h1 = __float22bfloat162_rn(
                make_float2(acc[i][n8][2] + b0, acc[i][n8][3] + b1));
            *(uint32_t*)(outp + (size_t)r0 * ld + col) = *(uint32_t*)&h0;
            *(uint32_t*)(outp + (size_t)(r0 + 8) * ld + col) = *(uint32_t*)&h1;
        }
    }
}

__global__ __launch_bounds__(256, 2) void fusion_mma_kernel(
    const float* __restrict__ fb) {
    extern __shared__ char smem[];
    const int bn = blockIdx.x * 128, bm = blockIdx.y * 128;
    float acc[2][8][4];
#pragma unroll
    for (int i = 0; i < 2; i++)
#pragma unroll
        for (int j = 0; j < 8; j++)
#pragma unroll
            for (int e = 0; e < 4; e++) acc[i][j][e] = 0.f;
    gemm_4x2_body(smem, g_A0 + (size_t)bm * 1024, 1024,
                  g_fwb + (size_t)bn * 1024, 1024, 16, acc);
    epilogue_bf16(acc, g_fusedb + (size_t)bm * DD + bn, DD, fb + bn);
}

__global__ __launch_bounds__(256, 2) void proj_mma_kernel() {
    extern __shared__ char smem[];
    const int bn = blockIdx.x * 128, bm = blockIdx.y * 128, z = blockIdx.z;
    float acc[2][8][4];
#pragma unroll
    for (int i = 0; i < 2; i++)
#pragma unroll
        for (int j = 0; j < 8; j++)
#pragma unroll
            for (int e = 0; e < 4; e++) acc[i][j][e] = 0.f;
    gemm_4x2_body(smem, g_fusedb + (size_t)bm * DD, DD,
                  g_Wt + (size_t)z * DD * DD + (size_t)bn * DD, DD, 8, acc);
    epilogue_bf16(acc, g_qk + (size_t)z * ROWS * DD + (size_t)bm * DD + bn,
                  DD, nullptr);
}

// ---------------------------------------------------------------------------
// Attention: 128x128x512 HMMA + fused scaling/softmax. 8x1 warp grid so each
// output row's 128 values live in one warp quad (shfl-only reductions).
// ---------------------------------------------------------------------------
__global__ __launch_bounds__(256, 1) void attn_mma_kernel(float* __restrict__ out) {
    extern __shared__ char smem[];
    __shared__ float sq[128], sk[128];
    const int kb = blockIdx.x, b = blockIdx.y;
    const int tid = threadIdx.x, lane = tid & 31, wid = tid >> 5;

    const __nv_bfloat16* qp = g_qk + ((size_t)kb * ROWS + (size_t)b * NN) * DD;
    const __nv_bfloat16* kp = g_qk + ((size_t)(KK + kb) * ROWS + (size_t)b * NN) * DD;

    const int base = kb * ROWS + b * NN;
    const float SCALE = 0.04419417382415922f;  // 1/sqrt(512)
    if (tid < 128) {
        sq[tid] = g_inv[base + tid] * SCALE;
        sk[tid] = g_inv[KK * ROWS + base + tid];
    }

    const uint32_t sb = smem_u32(smem);
    load_tile(sb, qp, DD, kp, DD, tid);
    CP_COMMIT();
    load_tile(sb + STAGE_BYTES, qp + 64, DD, kp + 64, DD, tid);
    CP_COMMIT();

    float acc[16][4];
#pragma unroll
    for (int j = 0; j < 16; j++)
#pragma unroll
        for (int e = 0; e < 4; e++) acc[j][e] = 0.f;

#pragma unroll 1
    for (int kt = 0; kt < 8; kt++) {
        if (kt + 1 < 8) CP_WAIT1(); else CP_WAIT0();
        __syncthreads();
        const uint32_t sA = sb + (kt & 1) * STAGE_BYTES;
        const uint32_t sB = sA + TILE_BYTES;
#pragma unroll
        for (int ks = 0; ks < 4; ks++) {
            const int ko = ks * 32 + (lane >> 4) * 16;
            uint32_t a[4], bf[8][4];
            ldsm4(a, sA + (wid * 16 + (lane & 15)) * ROWB + ko);
#pragma unroll
            for (int j = 0; j < 8; j++)
                ldsm4(bf[j], sB + (j * 16 + (lane & 15)) * ROWB + ko);
#pragma unroll
            for (int j = 0; j < 8; j++) {
                mma_bf16(acc[2 * j],     a, bf[j][0], bf[j][2]);
                mma_bf16(acc[2 * j + 1], a, bf[j][1], bf[j][3]);
            }
        }
        __syncthreads();
        if (kt + 2 < 8) {
            load_tile(sb + (kt & 1) * STAGE_BYTES,
                      qp + (kt + 2) * 64, DD, kp + (kt + 2) * 64, DD, tid);
            CP_COMMIT();
        }
    }

    // Scale by norms; softmax. Thread owns rows r0, r0+8; cols n8*8+qc(+1).
    const int qr = lane >> 2, qc = (lane & 3) * 2;
    const int r0 = wid * 16 + qr, r1 = r0 + 8;
    const float si0 = sq[r0], si1 = sq[r1];

    float m0 = -1e30f, m1 = -1e30f;
#pragma unroll
    for (int n8 = 0; n8 < 16; n8++) {
        const int col = n8 * 8 + qc;
        const float k0 = sk[col], k1 = sk[col + 1];
        acc[n8][0] *= si0 * k0; acc[n8][1] *= si0 * k1;
        acc[n8][2] *= si1 * k0; acc[n8][3] *= si1 * k1;
        m0 = fmaxf(m0, fmaxf(acc[n8][0], acc[n8][1]));
        m1 = fmaxf(m1, fmaxf(acc[n8][2], acc[n8][3]));
    }
#pragma unroll
    for (int msk = 1; msk <= 2; msk <<= 1) {
        m0 = fmaxf(m0, __shfl_xor_sync(0xffffffffu, m0, msk));
        m1 = fmaxf(m1, __shfl_xor_sync(0xffffffffu, m1, msk));
    }
    float s0 = 0.f, s1 = 0.f;
#pragma unroll
    for (int n8 = 0; n8 < 16; n8++) {
        acc[n8][0] = __expf(acc[n8][0] - m0); s0 += acc[n8][0];
        acc[n8][1] = __expf(acc[n8][1] - m0); s0 += acc[n8][1];
        acc[n8][2] = __expf(acc[n8][2] - m1); s1 += acc[n8][2];
        acc[n8][3] = __expf(acc[n8][3] - m1); s1 += acc[n8][3];
    }
#pragma unroll
    for (int msk = 1; msk <= 2; msk <<= 1) {
        s0 += __shfl_xor_sync(0xffffffffu, s0, msk);
        s1 += __shfl_xor_sync(0xffffffffu, s1, msk);
    }
    const float i0 = 1.0f / s0, i1 = 1.0f / s1;

    float* o0 = out + ALPHA_OFF + (((size_t)b * KK + kb) * NN + r0) * NN;
    float* o1 = out + ALPHA_OFF + (((size_t)b * KK + kb) * NN + r1) * NN;
#pragma unroll
    for (int n8 = 0; n8 < 16; n8++) {
        const int col = n8 * 8 + qc;
        float2 v0 = {acc[n8][0] * i0, acc[n8][1] * i0};
        float2 v1 = {acc[n8][2] * i1, acc[n8][3] * i1};
        *(float2*)(o0 + col) = v0;
        *(float2*)(o1 + col) = v1;
    }
}

// ---------------------------------------------------------------------------
// bias_log = log(max(0.01 * mean_b(alpha), 1e-6)) broadcast over b.
// ---------------------------------------------------------------------------
__global__ __launch_bounds__(256) void bias_kernel(float* __restrict__ out) {
    const int idx = blockIdx.x * blockDim.x + threadIdx.x;
    if (idx >= PLANE) return;
    float s = 0.0f;
#pragma unroll 8
    for (int b = 0; b < BB; b++)
        s += out[ALPHA_OFF + (size_t)b * PLANE + idx];
    float bias = logf(fmaxf(s * (0.01f / 32.0f), 1e-6f));
#pragma unroll 8
    for (int b = 0; b < BB; b++)
        out[(size_t)b * PLANE + idx] = bias;
}

// ---------------------------------------------------------------------------
// Launch
// ---------------------------------------------------------------------------
extern "C" void kernel_launch(void* const* d_in, const int* in_sizes, int n_in,
                              void* d_out, int out_size) {
    const float* desc = (const float*)d_in[0];   // [32,128,512]
    const float* nv   = (const float*)d_in[1];   // [32,128,512]
    const float* Wq   = (const float*)d_in[2];   // [8,512,512]
    const float* Wk   = (const float*)d_in[3];   // [8,512,512]
    const float* fw   = (const float*)d_in[4];   // [512,1024]
    const float* fb   = (const float*)d_in[5];   // [512]
    float* out = (float*)d_out;                  // [bias_log | alpha]

    cudaFuncSetAttribute(fusion_mma_kernel,
                         cudaFuncAttributeMaxDynamicSharedMemorySize, SMEM_BYTES);
    cudaFuncSetAttribute(proj_mma_kernel,
                         cudaFuncAttributeMaxDynamicSharedMemorySize, SMEM_BYTES);
    cudaFuncSetAttribute(attn_mma_kernel,
                         cudaFuncAttributeMaxDynamicSharedMemorySize, SMEM_BYTES);

    // bf16 conversions: concat(desc,nv) + fusion_w, and W^T
    convert_inputs<<<2304, 256>>>(desc, nv, fw);
    transpose_w<<<dim3(16, 16, 16), dim3(32, 8)>>>(Wq, Wk);

    // fusion = [desc|nv] @ fw^T + fb  (HMMA, K=1024)
    fusion_mma_kernel<<<dim3(4, 32), 256, SMEM_BYTES>>>(fb);

    // q/k projections: 16 batched 4096x512x512 GEMMs (HMMA)
    proj_mma_kernel<<<dim3(4, 32, 16), 256, SMEM_BYTES>>>();

    // inverse row norms of bf16 q/k
    rownorm_kernel<<<8192, 256>>>();

    // logits + softmax -> alpha (HMMA + fused epilogue)
    attn_mma_kernel<<<dim3(8, 32), 256, SMEM_BYTES>>>(out);

    // EMA mean + log -> bias_log broadcast
    bias_kernel<<<PLANE / 256, 256>>>(out);
}